// round 17
// baseline (speedup 1.0000x reference)
#include <cuda_runtime.h>
#include <cuda_bf16.h>
#include <math.h>

#define DI __device__ __forceinline__
typedef unsigned long long u64;

// ---------------- scratch (device globals: no allocation) ----------------
__device__ float    g_pooled[8192 * 64];
__device__ float    g_czb[8192 * 64];
__device__ float    g_tvec[200 * 64];
__device__ float    g_sr[200], g_srm1[200], g_c1[200], g_c2[200], g_sig[200];
__device__ unsigned g_k0[200], g_k1[200];

static constexpr int P  = 68;  // (unused by sampler now; kept for enc kernels)
static constexpr int PD = 66;  // u64 pitch for duplicated X/H tiles (even!)

// ---------------- packed f32x2 helpers (sm_103a FFMA2 path) ----------------
DI u64 pk2(float a, float b) {
  u64 r; asm("mov.b64 %0,{%1,%2};" : "=l"(r) : "f"(a), "f"(b)); return r;
}
DI void up2(u64 v, float& a, float& b) {
  asm("mov.b64 {%0,%1},%2;" : "=f"(a), "=f"(b) : "l"(v));
}
DI u64 f2fma(u64 a, u64 b, u64 c) {
  u64 d; asm("fma.rn.f32x2 %0,%1,%2,%3;" : "=l"(d) : "l"(a), "l"(b), "l"(c));
  return d;
}

// ---------------- JAX threefry2x32 (bit-exact) ----------------
DI void tf2x32(unsigned k0, unsigned k1, unsigned x0, unsigned x1,
               unsigned& o0, unsigned& o1) {
  unsigned k2 = k0 ^ k1 ^ 0x1BD11BDAu;
  x0 += k0; x1 += k1;
#define TFR(r) { x0 += x1; x1 = __funnelshift_l(x1, x1, (r)); x1 ^= x0; }
  TFR(13) TFR(15) TFR(26) TFR(6)
  x0 += k1; x1 += k2 + 1u;
  TFR(17) TFR(29) TFR(16) TFR(24)
  x0 += k2; x1 += k0 + 2u;
  TFR(13) TFR(15) TFR(26) TFR(6)
  x0 += k0; x1 += k1 + 3u;
  TFR(17) TFR(29) TFR(16) TFR(24)
  x0 += k1; x1 += k2 + 4u;
  TFR(13) TFR(15) TFR(26) TFR(6)
  x0 += k2; x1 += k0 + 5u;
#undef TFR
  o0 = x0; o1 = x1;
}

// partitionable threefry random bits for flat index i
DI unsigned jax_bits(unsigned k0, unsigned k1, unsigned i) {
  unsigned o0, o1;
  tf2x32(k0, k1, 0u, i, o0, o1);
  return o0 ^ o1;
}

// JAX normal(): uniform in [-1+2^-24, 1) then sqrt(2)*erfinv (XLA f32 poly)
DI float bits_to_normal(unsigned bits) {
  float f = __uint_as_float((bits >> 9) | 0x3f800000u) - 1.0f;   // [0,1)
  float u = fmaf(f, 2.0f, -0.99999994f);
  u = fmaxf(u, -0.99999994f);
  float w = -__logf(fmaf(u, -u, 1.0f));
  float ws = w - 2.5f;
  float p1 = 2.81022636e-08f;
  p1 = fmaf(p1, ws, 3.43273939e-07f);
  p1 = fmaf(p1, ws, -3.5233877e-06f);
  p1 = fmaf(p1, ws, -4.39150654e-06f);
  p1 = fmaf(p1, ws, 0.00021858087f);
  p1 = fmaf(p1, ws, -0.00125372503f);
  p1 = fmaf(p1, ws, -0.00417768164f);
  p1 = fmaf(p1, ws, 0.246640727f);
  p1 = fmaf(p1, ws, 1.50140941f);
  float wb = sqrtf(w) - 3.0f;
  float p2 = -0.000200214257f;
  p2 = fmaf(p2, wb, 0.000100950558f);
  p2 = fmaf(p2, wb, 0.00134934322f);
  p2 = fmaf(p2, wb, -0.00367342844f);
  p2 = fmaf(p2, wb, 0.00573950773f);
  p2 = fmaf(p2, wb, -0.0076224613f);
  p2 = fmaf(p2, wb, 0.00943887047f);
  p2 = fmaf(p2, wb, 1.00167406f);
  p2 = fmaf(p2, wb, 2.83297682f);
  float p = (w < 5.0f) ? p1 : p2;
  return 1.41421356f * (p * u);
}

// ---------------- setup: schedule, fold_in keys, tvec ----------------
__global__ void k_setup(const float* __restrict__ Wt,
                        const float* __restrict__ bt,
                        const float* __restrict__ bin) {
  int tid = threadIdx.x;
  __shared__ float fr[32];
  if (tid == 0) {
    double acp = 1.0;
    const double bA = 5e-4, bB = 0.1;  // scale = 1000/200 = 5
    for (int i = 0; i < 200; ++i) {
      double beta  = bA + (bB - bA) * (double)i / 199.0;
      double alpha = 1.0 - beta;
      double acp_prev = acp;
      acp *= alpha;
      g_sr[i]   = (float)sqrt(1.0 / acp);
      g_srm1[i] = (float)sqrt(1.0 / acp - 1.0);
      double pv = beta * (1.0 - acp_prev) / (1.0 - acp);
      g_sig[i]  = (i == 0) ? 0.0f : (float)sqrt(pv);
      g_c1[i]   = (float)(beta * sqrt(acp_prev) / (1.0 - acp));
      g_c2[i]   = (float)((1.0 - acp_prev) * sqrt(alpha) / (1.0 - acp));
    }
  }
  if (tid < 200) {  // fold_in(key(2)=[0,2], t)
    unsigned o0, o1;
    tf2x32(0u, 2u, 0u, (unsigned)tid, o0, o1);
    g_k0[tid] = o0; g_k1[tid] = o1;
  }
  if (tid < 32)
    fr[tid] = expf(-(logf(10000.0f) * (float)tid) / 32.0f);
  __syncthreads();
  // tvec[t][c] = b_in[c] + b_t[c] + sum_h temb_t[h] * W_t[h][c]
  for (int e = tid; e < 200 * 64; e += blockDim.x) {
    int t = e >> 6, c = e & 63;
    float acc = bin[c] + bt[c];
    for (int h = 0; h < 32; ++h) {
      float ang = (float)t * fr[h];
      float s, cz;
      sincosf(ang, &s, &cz);
      acc += cz * Wt[h * 64 + c] + s * Wt[(h + 32) * 64 + c];
    }
    g_tvec[e] = acc;
  }
}

// ---------------- pooled embedding: warp per row ----------------
__global__ void k_pool(const int* __restrict__ seq,
                       const float* __restrict__ emb) {
  int w = threadIdx.x >> 5, lane = threadIdx.x & 31;
  int row = blockIdx.x * 8 + w;
  const int* s = seq + row * 100;
  int cnt = 0;
  for (int l = lane; l < 100; l += 32) cnt += (s[l] != 0);
  for (int o = 16; o; o >>= 1) cnt += __shfl_xor_sync(0xffffffffu, cnt, o);
  float a0 = 0.f, a1 = 0.f;
  for (int l = 0; l < 100; ++l) {
    int id = __ldg(s + l);
    float2 v = *(const float2*)(emb + (size_t)id * 64 + lane * 2);
    a0 += v.x; a1 += v.y;
  }
  float sc = sqrtf((float)cnt);
  g_pooled[row * 64 + lane * 2]     = a0 / sc;
  g_pooled[row * 64 + lane * 2 + 1] = a1 / sc;
}

// ---------------- encoder MLP + cond projection: warp per row ----------------
__global__ void k_enc(const float* __restrict__ W1, const float* __restrict__ b1,
                      const float* __restrict__ W2, const float* __restrict__ b2,
                      const float* __restrict__ Wc, const float* __restrict__ bc) {
  __shared__ float sp[8][64], shh[8][256], smu[8][64];
  int w = threadIdx.x >> 5, lane = threadIdx.x & 31;
  int row = blockIdx.x * 8 + w;
  sp[w][lane * 2]     = g_pooled[row * 64 + lane * 2];
  sp[w][lane * 2 + 1] = g_pooled[row * 64 + lane * 2 + 1];
  __syncwarp();
  for (int jj = 0; jj < 8; ++jj) {
    int j = lane + 32 * jj;
    float acc = b1[j];
    for (int d = 0; d < 64; ++d) acc = fmaf(sp[w][d], W1[d * 256 + j], acc);
    shh[w][j] = fmaxf(acc, 0.0f);
  }
  __syncwarp();
  for (int cc = 0; cc < 2; ++cc) {
    int c = lane + 32 * cc;
    float acc = b2[c];
    for (int k = 0; k < 256; ++k) acc = fmaf(shh[w][k], W2[k * 128 + c], acc);
    smu[w][c] = acc;
  }
  __syncwarp();
  for (int cc = 0; cc < 2; ++cc) {
    int c = lane + 32 * cc;
    float acc = bc[c];
    for (int d = 0; d < 64; ++d) acc = fmaf(smu[w][d], Wc[d * 64 + c], acc);
    g_czb[row * 64 + c] = acc;
  }
}

// ---------------- persistent DDPM sampler: 64 rows / block, 512 threads ----------------
// Warp-local dataflow (warp w owns X/H rows {2w,2w+1,2w+32,2w+33}) => syncwarp only.
// X and H live in smem DUPLICATED: element k stored as packed (x,x) u64 so the
// GEMM inner loop feeds fma.rn.f32x2 (FFMA2) directly from ld.shared, with no
// per-FMA broadcast MOVs. Weight float4s reinterpret as ulonglong2 (lanes c,c+1).
__global__ void __launch_bounds__(512, 1)
k_sample(const float* __restrict__ Win, const float* __restrict__ Wout,
         const float* __restrict__ bout, float* __restrict__ out) {
  extern __shared__ float smf[];
  float* WinS  = smf;                    // 4096 floats
  float* WoutS = smf + 4096;             // 4096
  float* tvS   = smf + 8192;             // 12800
  u64*   Xd    = (u64*)&smf[20992];      // 64*PD u64 (duplicated lanes)
  u64*   Hd    = Xd + 64 * PD;           // 64*PD u64
  __shared__ float s_sr[200], s_sm[200], s_c1[200], s_c2[200], s_sg[200];
  __shared__ unsigned s_k0[200], s_k1[200];

  int tid = threadIdx.x;
  for (int i = tid; i < 4096; i += 512) { WinS[i] = Win[i]; WoutS[i] = Wout[i]; }
  for (int i = tid; i < 12800; i += 512) tvS[i] = g_tvec[i];
  if (tid < 200) {
    s_sr[tid] = g_sr[tid]; s_sm[tid] = g_srm1[tid]; s_c1[tid] = g_c1[tid];
    s_c2[tid] = g_c2[tid]; s_sg[tid] = g_sig[tid];
    s_k0[tid] = g_k0[tid]; s_k1[tid] = g_k1[tid];
  }

  int cq = tid & 15, rw = tid >> 4;   // rw in 0..31
  int c0 = cq * 4;
  int r0 = rw, r1 = rw + 32;
  int g0 = blockIdx.x * 64 + r0;
  int g1 = g0 + 32;
  unsigned b0 = (unsigned)(g0 * 64 + c0);
  unsigned b1 = (unsigned)(g1 * 64 + c0);

  float4 cz0 = *(const float4*)(g_czb + g0 * 64 + c0);
  float4 cz1 = *(const float4*)(g_czb + g1 * 64 + c0);
  float4 bo  = *(const float4*)(bout + c0);
  u64 boA = pk2(bo.x, bo.y), boB = pk2(bo.z, bo.w);

  // x_init ~ normal(key(1) = [0,1]), stored duplicated
  {
    float x00 = bits_to_normal(jax_bits(0u, 1u, b0 + 0));
    float x01 = bits_to_normal(jax_bits(0u, 1u, b0 + 1));
    float x02 = bits_to_normal(jax_bits(0u, 1u, b0 + 2));
    float x03 = bits_to_normal(jax_bits(0u, 1u, b0 + 3));
    float x10 = bits_to_normal(jax_bits(0u, 1u, b1 + 0));
    float x11 = bits_to_normal(jax_bits(0u, 1u, b1 + 1));
    float x12 = bits_to_normal(jax_bits(0u, 1u, b1 + 2));
    float x13 = bits_to_normal(jax_bits(0u, 1u, b1 + 3));
    ulonglong2 v;
    v.x = pk2(x00, x00); v.y = pk2(x01, x01); *(ulonglong2*)&Xd[r0 * PD + c0]     = v;
    v.x = pk2(x02, x02); v.y = pk2(x03, x03); *(ulonglong2*)&Xd[r0 * PD + c0 + 2] = v;
    v.x = pk2(x10, x10); v.y = pk2(x11, x11); *(ulonglong2*)&Xd[r1 * PD + c0]     = v;
    v.x = pk2(x12, x12); v.y = pk2(x13, x13); *(ulonglong2*)&Xd[r1 * PD + c0 + 2] = v;
  }
  __syncthreads();   // weights/tvec visible to all; X rows only need own warp

  for (int t = 199; t >= 0; --t) {
    float sr = s_sr[t], smm = s_sm[t], c1c = s_c1[t], c2c = s_c2[t], sg = s_sg[t];
    unsigned kk0 = s_k0[t], kk1 = s_k1[t];

    // ---- GEMM1: H = silu(X @ W_in + tvec[t] + czb) ----
    float4 tv = *(float4*)&tvS[t * 64 + c0];
    u64 acc0A = pk2(tv.x + cz0.x, tv.y + cz0.y);
    u64 acc0B = pk2(tv.z + cz0.z, tv.w + cz0.w);
    u64 acc1A = pk2(tv.x + cz1.x, tv.y + cz1.y);
    u64 acc1B = pk2(tv.z + cz1.z, tv.w + cz1.w);
#pragma unroll
    for (int k4 = 0; k4 < 64; k4 += 4) {
      ulonglong2 xa0 = *(ulonglong2*)&Xd[r0 * PD + k4];
      ulonglong2 xb0 = *(ulonglong2*)&Xd[r0 * PD + k4 + 2];
      ulonglong2 xa1 = *(ulonglong2*)&Xd[r1 * PD + k4];
      ulonglong2 xb1 = *(ulonglong2*)&Xd[r1 * PD + k4 + 2];
      u64 a0[4] = {xa0.x, xa0.y, xb0.x, xb0.y};
      u64 a1[4] = {xa1.x, xa1.y, xb1.x, xb1.y};
#pragma unroll
      for (int kk = 0; kk < 4; ++kk) {
        ulonglong2 wv = *(const ulonglong2*)&WinS[(k4 + kk) * 64 + c0];
        acc0A = f2fma(a0[kk], wv.x, acc0A);
        acc0B = f2fma(a0[kk], wv.y, acc0B);
        acc1A = f2fma(a1[kk], wv.x, acc1A);
        acc1B = f2fma(a1[kk], wv.y, acc1B);
      }
    }
    {
      float v0, v1, v2, v3, w0, w1, w2, w3;
      up2(acc0A, v0, v1); up2(acc0B, v2, v3);
      up2(acc1A, w0, w1); up2(acc1B, w2, w3);
      float h00 = __fdividef(v0, 1.0f + __expf(-v0));
      float h01 = __fdividef(v1, 1.0f + __expf(-v1));
      float h02 = __fdividef(v2, 1.0f + __expf(-v2));
      float h03 = __fdividef(v3, 1.0f + __expf(-v3));
      float h10 = __fdividef(w0, 1.0f + __expf(-w0));
      float h11 = __fdividef(w1, 1.0f + __expf(-w1));
      float h12 = __fdividef(w2, 1.0f + __expf(-w2));
      float h13 = __fdividef(w3, 1.0f + __expf(-w3));
      ulonglong2 v;
      v.x = pk2(h00, h00); v.y = pk2(h01, h01); *(ulonglong2*)&Hd[r0 * PD + c0]     = v;
      v.x = pk2(h02, h02); v.y = pk2(h03, h03); *(ulonglong2*)&Hd[r0 * PD + c0 + 2] = v;
      v.x = pk2(h10, h10); v.y = pk2(h11, h11); *(ulonglong2*)&Hd[r1 * PD + c0]     = v;
      v.x = pk2(h12, h12); v.y = pk2(h13, h13); *(ulonglong2*)&Hd[r1 * PD + c0 + 2] = v;
    }
    __syncwarp();   // H rows are warp-local

    // ---- noise (independent ALU stream; interleaves with GEMM2 FMAs) ----
    float nz[8];
#pragma unroll
    for (int j = 0; j < 4; ++j) nz[j]     = bits_to_normal(jax_bits(kk0, kk1, b0 + (unsigned)j));
#pragma unroll
    for (int j = 0; j < 4; ++j) nz[4 + j] = bits_to_normal(jax_bits(kk0, kk1, b1 + (unsigned)j));

    // ---- GEMM2: eps = H @ W_out + b_out ----
    u64 e0A = boA, e0B = boB, e1A = boA, e1B = boB;
#pragma unroll
    for (int k4 = 0; k4 < 64; k4 += 4) {
      ulonglong2 xa0 = *(ulonglong2*)&Hd[r0 * PD + k4];
      ulonglong2 xb0 = *(ulonglong2*)&Hd[r0 * PD + k4 + 2];
      ulonglong2 xa1 = *(ulonglong2*)&Hd[r1 * PD + k4];
      ulonglong2 xb1 = *(ulonglong2*)&Hd[r1 * PD + k4 + 2];
      u64 a0[4] = {xa0.x, xa0.y, xb0.x, xb0.y};
      u64 a1[4] = {xa1.x, xa1.y, xb1.x, xb1.y};
#pragma unroll
      for (int kk = 0; kk < 4; ++kk) {
        ulonglong2 wv = *(const ulonglong2*)&WoutS[(k4 + kk) * 64 + c0];
        e0A = f2fma(a0[kk], wv.x, e0A);
        e0B = f2fma(a0[kk], wv.y, e0B);
        e1A = f2fma(a1[kk], wv.x, e1A);
        e1B = f2fma(a1[kk], wv.y, e1B);
      }
    }

    // ---- elementwise update (scalar; reads lo lanes of duplicated X) ----
    {
      float e00, e01, e02, e03, e10, e11, e12, e13;
      up2(e0A, e00, e01); up2(e0B, e02, e03);
      up2(e1A, e10, e11); up2(e1B, e12, e13);
      float e0v[4] = {e00, e01, e02, e03};
      float e1v[4] = {e10, e11, e12, e13};

      ulonglong2 xo0a = *(ulonglong2*)&Xd[r0 * PD + c0];
      ulonglong2 xo0b = *(ulonglong2*)&Xd[r0 * PD + c0 + 2];
      ulonglong2 xo1a = *(ulonglong2*)&Xd[r1 * PD + c0];
      ulonglong2 xo1b = *(ulonglong2*)&Xd[r1 * PD + c0 + 2];
      float xo0[4], xo1[4], dum;
      up2(xo0a.x, xo0[0], dum); up2(xo0a.y, xo0[1], dum);
      up2(xo0b.x, xo0[2], dum); up2(xo0b.y, xo0[3], dum);
      up2(xo1a.x, xo1[0], dum); up2(xo1a.y, xo1[1], dum);
      up2(xo1b.x, xo1[2], dum); up2(xo1b.y, xo1[3], dum);

      float n0[4], n1[4];
#pragma unroll
      for (int j = 0; j < 4; ++j) {
        float x0 = sr * xo0[j] - smm * e0v[j];
        x0 = fminf(fmaxf(x0, -1.0f), 1.0f);
        n0[j] = c1c * x0 + c2c * xo0[j] + sg * nz[j];
      }
#pragma unroll
      for (int j = 0; j < 4; ++j) {
        float x0 = sr * xo1[j] - smm * e1v[j];
        x0 = fminf(fmaxf(x0, -1.0f), 1.0f);
        n1[j] = c1c * x0 + c2c * xo1[j] + sg * nz[4 + j];
      }
      ulonglong2 v;
      v.x = pk2(n0[0], n0[0]); v.y = pk2(n0[1], n0[1]); *(ulonglong2*)&Xd[r0 * PD + c0]     = v;
      v.x = pk2(n0[2], n0[2]); v.y = pk2(n0[3], n0[3]); *(ulonglong2*)&Xd[r0 * PD + c0 + 2] = v;
      v.x = pk2(n1[0], n1[0]); v.y = pk2(n1[1], n1[1]); *(ulonglong2*)&Xd[r1 * PD + c0]     = v;
      v.x = pk2(n1[2], n1[2]); v.y = pk2(n1[3], n1[3]); *(ulonglong2*)&Xd[r1 * PD + c0 + 2] = v;
    }
    __syncwarp();   // X rows are warp-local
  }

  // ---- write back (lo lanes) ----
  {
    ulonglong2 xa = *(ulonglong2*)&Xd[r0 * PD + c0];
    ulonglong2 xb = *(ulonglong2*)&Xd[r0 * PD + c0 + 2];
    ulonglong2 ya = *(ulonglong2*)&Xd[r1 * PD + c0];
    ulonglong2 yb = *(ulonglong2*)&Xd[r1 * PD + c0 + 2];
    float4 o0, o1; float dum;
    up2(xa.x, o0.x, dum); up2(xa.y, o0.y, dum);
    up2(xb.x, o0.z, dum); up2(xb.y, o0.w, dum);
    up2(ya.x, o1.x, dum); up2(ya.y, o1.y, dum);
    up2(yb.x, o1.z, dum); up2(yb.y, o1.w, dum);
    *(float4*)(out + g0 * 64 + c0) = o0;
    *(float4*)(out + g1 * 64 + c0) = o1;
  }
}

// ---------------- launch ----------------
extern "C" void kernel_launch(void* const* d_in, const int* in_sizes, int n_in,
                              void* d_out, int out_size) {
  if (n_in < 14) return;
  const int*   seq  = (const int*)d_in[0];
  const float* emb  = (const float*)d_in[1];
  const float* W1   = (const float*)d_in[2];
  const float* b1   = (const float*)d_in[3];
  const float* W2   = (const float*)d_in[4];
  const float* b2   = (const float*)d_in[5];
  const float* Win  = (const float*)d_in[6];
  const float* bin  = (const float*)d_in[7];
  const float* Wt   = (const float*)d_in[8];
  const float* bt   = (const float*)d_in[9];
  const float* Wc   = (const float*)d_in[10];
  const float* bc   = (const float*)d_in[11];
  const float* Wout = (const float*)d_in[12];
  const float* bout = (const float*)d_in[13];
  float* out = (float*)d_out;

  int B = in_sizes[0] / 100;        // 8192
  int rowBlocks = B / 8;            // warp-per-row kernels
  int sampBlocks = B / 64;          // 64 rows per sampler block

  k_setup<<<1, 256>>>(Wt, bt, bin);
  k_pool<<<rowBlocks, 256>>>(seq, emb);
  k_enc<<<rowBlocks, 256>>>(W1, b1, W2, b2, Wc, bc);

  size_t smem = (size_t)20992 * sizeof(float) + (size_t)2 * 64 * PD * sizeof(u64);
  cudaFuncSetAttribute(k_sample, cudaFuncAttributeMaxDynamicSharedMemorySize,
                       (int)smem);
  k_sample<<<sampBlocks, 512, smem>>>(Win, Wout, bout, out);
}